// round 2
// baseline (speedup 1.0000x reference)
#include <cuda_runtime.h>
#include <cuda_bf16.h>

// VQ-VAE vector quantization, bit-replicating the JAX/XLA:CPU fp32 pipeline:
//   a_r = strict sequential sum_d fl(x_rd^2)                    (row norms)
//   b_k = strict sequential sum_d fl(dict_dk^2)                 (code norms)
//   s_rk = sequential-k FMA chain  sum_d fma(x_rd, dict_dk)     (Eigen gebp)
//   D_rk = fl( fl(a_r + b_k) - 2*s_rk )                         (2*s exact)
//   code = argmin_k D (first index on ties)
//   q = gather(dict^T, code);  out = fl(x + fl(q - x))          (straight-through)
//   loss = 1.25 * mean(fl((x-q)^2))

#define D_DIM 256
#define K_CODES 1024
#define N_ROWS 65536
#define BM 128     // rows per block
#define BK 128     // codes per chunk
#define DK 32      // d per smem k-step

__device__ float  g_dictT[K_CODES * D_DIM]; // [code][d]
__device__ float  g_bnorm[K_CODES];
__device__ float  g_anorm[N_ROWS];
__device__ double g_loss;

// ---------------------------------------------------------------------------
// Prep: per-code strict-sequential norm (d ascending, mul+add, no fma) and
// transpose dict [256][1024] -> dictT [1024][256]. One thread per code.
// ---------------------------------------------------------------------------
__global__ void vq_prep_dict(const float* __restrict__ dict) {
    int k = blockIdx.x * blockDim.x + threadIdx.x;
    if (k >= K_CODES) return;
    float b = 0.f;
    for (int d = 0; d < D_DIM; d++) {
        float v = dict[d * K_CODES + k];
        b = __fadd_rn(b, __fmul_rn(v, v));
        g_dictT[k * D_DIM + d] = v;
    }
    g_bnorm[k] = b;
    if (k == 0) g_loss = 0.0;
}

// ---------------------------------------------------------------------------
// Prep: per-row strict-sequential norm (d ascending, mul+add). 1 thread/row.
// ---------------------------------------------------------------------------
__global__ void vq_rownorm(const float* __restrict__ x) {
    int r = blockIdx.x * blockDim.x + threadIdx.x;
    const float* p = x + (long)r * D_DIM;
    float a = 0.f;
    #pragma unroll 4
    for (int d = 0; d < D_DIM; d += 8) {
        float4 u = *(const float4*)&p[d];
        float4 w = *(const float4*)&p[d + 4];
        a = __fadd_rn(a, __fmul_rn(u.x, u.x));
        a = __fadd_rn(a, __fmul_rn(u.y, u.y));
        a = __fadd_rn(a, __fmul_rn(u.z, u.z));
        a = __fadd_rn(a, __fmul_rn(u.w, u.w));
        a = __fadd_rn(a, __fmul_rn(w.x, w.x));
        a = __fadd_rn(a, __fmul_rn(w.y, w.y));
        a = __fadd_rn(a, __fmul_rn(w.z, w.z));
        a = __fadd_rn(a, __fmul_rn(w.w, w.w));
    }
    g_anorm[r] = a;
}

// ---------------------------------------------------------------------------
// Main: fused GEMM (sequential-k FMA chain) + running argmin + gather + loss.
// grid = N/BM, block = 256 (16x16 thread grid, 8x8 register tiles)
// ---------------------------------------------------------------------------
__global__ __launch_bounds__(256) void vq_main(const float* __restrict__ x,
                                               const float* __restrict__ dict,
                                               float* __restrict__ out) {
    __shared__ float As[DK][BM];      // x tile, transposed (d-major)
    __shared__ float Bs[DK][BK];      // dict tile (d-major, natural layout)
    __shared__ float en[BK];
    __shared__ float sh_a[BM];
    __shared__ float bestv[BM];
    __shared__ int   besti[BM];
    __shared__ double red[8];

    const int tid = threadIdx.x;
    const int tx  = tid & 15;         // code-tile lane (8 codes)
    const int ty  = tid >> 4;         // row-tile lane  (8 rows)
    const long row0 = (long)blockIdx.x * BM;

    if (tid < BM) {
        bestv[tid] = 3.4e38f; besti[tid] = 0;
        sh_a[tid]  = g_anorm[row0 + tid];
    }
    __syncthreads();

    float a_reg[8];
    #pragma unroll
    for (int i = 0; i < 8; i++) a_reg[i] = sh_a[ty * 8 + i];

    float acc[8][8];

    for (int cc = 0; cc < K_CODES; cc += BK) {
        __syncthreads();
        if (tid < BK) en[tid] = g_bnorm[cc + tid];
        #pragma unroll
        for (int i = 0; i < 8; i++)
            #pragma unroll
            for (int j = 0; j < 8; j++) acc[i][j] = 0.f;

        for (int dd = 0; dd < D_DIM; dd += DK) {
            __syncthreads();
            // load x tile [BM rows][DK d] transposed into As[d][row]
            {
                int d4 = (tid & 7) * 4;
                int r  = tid >> 3;
                #pragma unroll
                for (int p = 0; p < 4; p++) {
                    int row = r + p * 32;
                    float4 v = *(const float4*)&x[(row0 + row) * D_DIM + dd + d4];
                    As[d4 + 0][row] = v.x; As[d4 + 1][row] = v.y;
                    As[d4 + 2][row] = v.z; As[d4 + 3][row] = v.w;
                }
            }
            // load dict tile [DK d][BK codes] (natural layout, coalesced)
            {
                int c4 = (tid & 31) * 4;
                int d  = tid >> 5;
                #pragma unroll
                for (int p = 0; p < 4; p++) {
                    int dr = d + p * 8;
                    *(float4*)&Bs[dr][c4] =
                        *(const float4*)&dict[(dd + dr) * K_CODES + cc + c4];
                }
            }
            __syncthreads();
            // sequential-k FMA chain (d ascending) per accumulator — matches
            // Eigen gebp's single-accumulator ascending-k fused chain bitwise.
            #pragma unroll
            for (int k = 0; k < DK; k++) {
                float a[8], b[8];
                *(float4*)(a)     = *(const float4*)&As[k][ty * 8];
                *(float4*)(a + 4) = *(const float4*)&As[k][ty * 8 + 4];
                *(float4*)(b)     = *(const float4*)&Bs[k][tx * 8];
                *(float4*)(b + 4) = *(const float4*)&Bs[k][tx * 8 + 4];
                #pragma unroll
                for (int i = 0; i < 8; i++)
                    #pragma unroll
                    for (int j = 0; j < 8; j++)
                        acc[i][j] = __fmaf_rn(a[i], b[j], acc[i][j]);
            }
        }

        // argmin update on D = fl( fl(a + b) - 2*s ), first-index tie-break
        #pragma unroll
        for (int i = 0; i < 8; i++) {
            float v;
            int   bi;
            #pragma unroll
            for (int j = 0; j < 8; j++) {
                float t  = __fadd_rn(a_reg[i], en[tx * 8 + j]);
                float vj = __fadd_rn(t, __fmul_rn(-2.0f, acc[i][j]));
                int   ij = cc + tx * 8 + j;
                if (j == 0 || vj < v) { v = vj; bi = ij; }
            }
            #pragma unroll
            for (int o = 8; o > 0; o >>= 1) {
                float ov = __shfl_down_sync(0xffffffffu, v,  o, 16);
                int   oi = __shfl_down_sync(0xffffffffu, bi, o, 16);
                if (ov < v || (ov == v && oi < bi)) { v = ov; bi = oi; }
            }
            if (tx == 0) {
                int row = ty * 8 + i;
                if (v < bestv[row]) { bestv[row] = v; besti[row] = bi; }
            }
        }
    }
    __syncthreads();

    // Epilogue: gather q, straight-through out = fl(x + fl(q - x)), loss sum.
    double lsum = 0.0;
    for (int r = 0; r < BM; r++) {
        int   idx = besti[r];
        float q   = g_dictT[idx * D_DIM + tid];  // tid = d (0..255), coalesced
        long  gi  = (row0 + r) * D_DIM + tid;
        float xv  = x[gi];
        out[gi] = __fadd_rn(xv, __fsub_rn(q, xv));
        float dq = __fsub_rn(xv, q);
        lsum += (double)__fmul_rn(dq, dq);
    }
    #pragma unroll
    for (int o = 16; o > 0; o >>= 1) lsum += __shfl_down_sync(0xffffffffu, lsum, o);
    if ((tid & 31) == 0) red[tid >> 5] = lsum;
    __syncthreads();
    if (tid == 0) {
        double s = 0.0;
        #pragma unroll
        for (int w = 0; w < 8; w++) s += red[w];
        atomicAdd(&g_loss, s);
    }
}

// ---------------------------------------------------------------------------
// Finalize: loss = 1.25 * (sum / numel)
// ---------------------------------------------------------------------------
__global__ void vq_finalize(float* __restrict__ out, int loss_idx, double inv_numel) {
    out[loss_idx] = (float)(1.25 * (g_loss * inv_numel));
}

extern "C" void kernel_launch(void* const* d_in, const int* in_sizes, int n_in,
                              void* d_out, int out_size) {
    const float* x    = (const float*)d_in[0];
    const float* dict = (const float*)d_in[1];
    int nx = in_sizes[0], nd = in_sizes[1];
    if (nx < nd) { const float* t = x; x = dict; dict = t; int s = nx; nx = nd; nd = s; }

    float* out = (float*)d_out;
    int rows = nx / D_DIM;   // 65536

    vq_prep_dict<<<K_CODES / 256, 256>>>(dict);
    vq_rownorm<<<rows / 256, 256>>>(x);
    vq_main<<<rows / BM, 256>>>(x, dict, out);
    vq_finalize<<<1, 1>>>(out, out_size - 1, 1.0 / (double)nx);
}